// round 1
// baseline (speedup 1.0000x reference)
#include <cuda_runtime.h>

// SymmetryControl, s.shape[1]==5 branch.
// x: [B,C,H,W] f32, s: [B,5] f32, w: [B,C,H,W] f32, out: [B,C,H,W] f32
// B=16, C=96, H=96, W=96 ; step = W/8 = 12.
//
// shift(x,n)[i]  = x[(i-n) mod W]
// flip(x,n)[i]   = x[(n-i) mod W]
// indices needed per output element i (W=96):
//   i90   = (i-24) mod 96 = (i+72)%96
//   i180  = (i+48)%96
//   i270  = (i+24)%96
//   i90f  = (23-i) mod 96
//   i180f = (47-i) mod 96
// All within one W-row -> stage the row in SMEM, compute in-place.

#define WDIM 96
#define ROWS_PER_BLOCK 8
#define BLOCK_THREADS (WDIM * ROWS_PER_BLOCK)

__global__ __launch_bounds__(BLOCK_THREADS)
void symmetry_control_kernel(const float* __restrict__ x,
                             const float* __restrict__ s,
                             const float* __restrict__ w,
                             float* __restrict__ out,
                             int rows_per_batch /* = C*H */)
{
    __shared__ float sx[ROWS_PER_BLOCK][WDIM];
    __shared__ float sw[ROWS_PER_BLOCK][WDIM];
    __shared__ float sg[5];

    const int i  = threadIdx.x;          // position in row, 0..95
    const int ry = threadIdx.y;          // row within block, 0..7
    const long long row = (long long)blockIdx.x * ROWS_PER_BLOCK + ry;
    const size_t base = (size_t)row * WDIM;

    // Stage this thread's element of x and w (fully coalesced: row is 384B,
    // 128B-aligned; each warp covers exactly one 128B segment).
    const float xv = x[base + i];
    const float wv = w[base + i];
    sx[ry][i] = xv;
    sw[ry][i] = wv;

    // One sigmoid set per block (all 8 rows share the same batch b because
    // rows_per_batch = 9216 is divisible by ROWS_PER_BLOCK).
    if (ry == 0 && i < 5) {
        const int b = (int)(((long long)blockIdx.x * ROWS_PER_BLOCK) / rows_per_batch);
        const float sv = s[b * 5 + i];
        sg[i] = 1.0f / (1.0f + __expf(-sv));
    }
    __syncthreads();

    // Rotation / mirror indices (branch-free adds, known at compile time mod W)
    int i90  = i + 72; if (i90  >= WDIM) i90  -= WDIM;
    int i180 = i + 48; if (i180 >= WDIM) i180 -= WDIM;
    int i270 = i + 24; if (i270 >= WDIM) i270 -= WDIM;
    int i90f  = 23 - i; if (i90f  < 0) i90f  += WDIM;
    int i180f = 47 - i; if (i180f < 0) i180f += WDIM;

    const float g0 = sg[0], g1 = sg[1], g2 = sg[2], g3 = sg[3], g4 = sg[4];

    const float w90   = g0 * sw[ry][i90];
    const float w180  = g1 * sw[ry][i180];
    const float w270  = g2 * sw[ry][i270];
    const float w90f  = g3 * sw[ry][i90f];
    const float w180f = g4 * sw[ry][i180f];

    float a = wv * xv;
    a = fmaf(w90,   sx[ry][i90],   a);
    a = fmaf(w180,  sx[ry][i180],  a);
    a = fmaf(w270,  sx[ry][i270],  a);
    a = fmaf(w90f,  sx[ry][i90f],  a);
    a = fmaf(w180f, sx[ry][i180f], a);

    const float denom = wv + w90 + w180 + w270 + w90f + w180f;

    out[base + i] = a / denom;
}

extern "C" void kernel_launch(void* const* d_in, const int* in_sizes, int n_in,
                              void* d_out, int out_size)
{
    const float* x = (const float*)d_in[0];
    const float* s = (const float*)d_in[1];
    const float* w = (const float*)d_in[2];
    float* out = (float*)d_out;

    // Derive dims defensively from sizes (shapes fixed: 16x96x96x96, s 16x5).
    const long long total = in_sizes[0];         // B*C*H*W
    const int B = in_sizes[1] / 5;               // 16
    const long long rows = total / WDIM;         // B*C*H
    const int rows_per_batch = (int)(rows / B);  // C*H = 9216

    const long long nblocks = rows / ROWS_PER_BLOCK;   // 18432
    dim3 block(WDIM, ROWS_PER_BLOCK);
    symmetry_control_kernel<<<(unsigned)nblocks, block>>>(x, s, w, out, rows_per_batch);
}

// round 2
// speedup vs baseline: 2.1140x; 2.1140x over previous
#include <cuda_runtime.h>

// SymmetryControl, s.shape[1]==5 branch. B=16, C=96, H=96, W=96, step=12.
// Per output element i (within a W-row):
//   i90=(i+72)%96  i180=(i+48)%96  i270=(i+24)%96  (shifts, order-preserving)
//   i90f=(23-i)%96 i180f=(47-i)%96                 (mirrors, order-reversing)
// In float4 units (t = i/4, W4 = 24):
//   shifts: (t+18)%24, (t+12)%24, (t+6)%24       -> aligned float4, in order
//   flips:  (5-t)%24,  (11-t)%24                 -> aligned float4, components reversed

#define W4 24          // 96 floats per row = 24 float4
#define RPB 16         // rows per block
#define BLOCK_THREADS (W4 * RPB)   // 384

__device__ __forceinline__ float sym_comp(
    float xv, float wv,
    float x90, float w90r, float x180, float w180r, float x270, float w270r,
    float xf90, float wf90r, float xf180, float wf180r,
    float g0, float g1, float g2, float g3, float g4)
{
    const float W90   = g0 * w90r;
    const float W180  = g1 * w180r;
    const float W270  = g2 * w270r;
    const float WF90  = g3 * wf90r;
    const float WF180 = g4 * wf180r;

    float a = wv * xv;
    a = fmaf(W90,   x90,   a);
    a = fmaf(W180,  x180,  a);
    a = fmaf(W270,  x270,  a);
    a = fmaf(WF90,  xf90,  a);
    a = fmaf(WF180, xf180, a);

    const float d = wv + W90 + W180 + W270 + WF90 + WF180;
    return __fdividef(a, d);
}

__global__ __launch_bounds__(BLOCK_THREADS)
void symmetry_control_v4(const float4* __restrict__ x4,
                         const float*  __restrict__ s,
                         const float4* __restrict__ w4,
                         float4* __restrict__ out4,
                         int rows_per_batch /* C*H = 9216 */)
{
    __shared__ float4 sx[RPB][W4 + 1];   // +1 float4 pad -> 4-bank rotation/row
    __shared__ float4 sw[RPB][W4 + 1];
    __shared__ float  sg[5];

    const int t  = threadIdx.x;          // float4 index within row, 0..23
    const int ry = threadIdx.y;          // row within block, 0..15
    const long long row = (long long)blockIdx.x * RPB + ry;
    const size_t base = (size_t)row * W4;

    const float4 xv = x4[base + t];
    const float4 wv = w4[base + t];
    sx[ry][t] = xv;
    sw[ry][t] = wv;

    // One sigmoid set per block; rows_per_batch (9216) divisible by RPB, so
    // the whole block shares one batch index.
    if (ry == 0 && t < 5) {
        const int b = (int)(((long long)blockIdx.x * RPB) / rows_per_batch);
        const float sv = s[b * 5 + t];
        sg[t] = 1.0f / (1.0f + __expf(-sv));
    }
    __syncthreads();

    int j90  = t + 18; if (j90  >= W4) j90  -= W4;
    int j180 = t + 12; if (j180 >= W4) j180 -= W4;
    int j270 = t + 6;  if (j270 >= W4) j270 -= W4;
    int f90  = 5  - t; if (f90  < 0)   f90  += W4;
    int f180 = 11 - t; if (f180 < 0)   f180 += W4;

    const float g0 = sg[0], g1 = sg[1], g2 = sg[2], g3 = sg[3], g4 = sg[4];

    const float4 x90   = sx[ry][j90],  w90   = sw[ry][j90];
    const float4 x180  = sx[ry][j180], w180  = sw[ry][j180];
    const float4 x270  = sx[ry][j270], w270  = sw[ry][j270];
    const float4 xf90  = sx[ry][f90],  wf90  = sw[ry][f90];
    const float4 xf180 = sx[ry][f180], wf180 = sw[ry][f180];

    float4 o;
    // component c of output pairs with component (3-c) of the flip vectors
    o.x = sym_comp(xv.x, wv.x, x90.x, w90.x, x180.x, w180.x, x270.x, w270.x,
                   xf90.w, wf90.w, xf180.w, wf180.w, g0, g1, g2, g3, g4);
    o.y = sym_comp(xv.y, wv.y, x90.y, w90.y, x180.y, w180.y, x270.y, w270.y,
                   xf90.z, wf90.z, xf180.z, wf180.z, g0, g1, g2, g3, g4);
    o.z = sym_comp(xv.z, wv.z, x90.z, w90.z, x180.z, w180.z, x270.z, w270.z,
                   xf90.y, wf90.y, xf180.y, wf180.y, g0, g1, g2, g3, g4);
    o.w = sym_comp(xv.w, wv.w, x90.w, w90.w, x180.w, w180.w, x270.w, w270.w,
                   xf90.x, wf90.x, xf180.x, wf180.x, g0, g1, g2, g3, g4);

    out4[base + t] = o;
}

extern "C" void kernel_launch(void* const* d_in, const int* in_sizes, int n_in,
                              void* d_out, int out_size)
{
    const float4* x4 = (const float4*)d_in[0];
    const float*  s  = (const float*)d_in[1];
    const float4* w4 = (const float4*)d_in[2];
    float4* out4 = (float4*)d_out;

    const long long total = in_sizes[0];          // B*C*H*W = 14,155,776
    const int B = in_sizes[1] / 5;                // 16
    const long long rows = total / 96;            // B*C*H = 147,456
    const int rows_per_batch = (int)(rows / B);   // 9216

    const long long nblocks = rows / RPB;         // 9216
    dim3 block(W4, RPB);
    symmetry_control_v4<<<(unsigned)nblocks, block>>>(x4, s, w4, out4, rows_per_batch);
}

// round 3
// speedup vs baseline: 2.8538x; 1.3500x over previous
#include <cuda_runtime.h>

// SymmetryControl (square-symmetry branch), B=16,C=96,H=96,W=96.
// Orbit-blocked: thread (row, tx in 0..5) owns float4 positions {tx,tx+6,tx+12,tx+18}
// of its 24-float4 row, computes those 4 outputs. Shift operands (+6,+12,+18 f4)
// are register-resident; flip operands live in partner orbit s=5-tx, exchanged
// via SMEM as p = x*w and w (since w_g * x_g == (w*x)_g).
//
// Element mapping: out elem i=4t+c:
//   shifts: f4 idx (t+18)%24, (t+12)%24, (t+6)%24, same component c
//   flips:  f4 idx (5-t)%24 and (11-t)%24, component 3-c (reversed)

#define W4  24
#define TPR 6            // threads per row
#define RPB 32           // rows per block
#define BLOCK_THREADS (TPR * RPB)   // 192
#define PITCH 25         // padded row pitch in float4

__global__ __launch_bounds__(BLOCK_THREADS)
void symmetry_control_orbit(const float4* __restrict__ x4,
                            const float*  __restrict__ s,
                            const float4* __restrict__ w4,
                            float4* __restrict__ out4,
                            int rows_per_batch /* C*H = 9216 */)
{
    __shared__ float4 sp[RPB][PITCH];   // p = x*w
    __shared__ float4 sv[RPB][PITCH];   // w
    __shared__ float  sg[5];

    const int tx = threadIdx.x;          // orbit id, 0..5
    const int ry = threadIdx.y;          // row within block
    const long long row = (long long)blockIdx.x * RPB + ry;
    const size_t base = (size_t)row * W4;

    float4 P[4], Wv[4];
#pragma unroll
    for (int k = 0; k < 4; k++) {
        const int pos = tx + 6 * k;
        const float4 xv = x4[base + pos];
        const float4 wv = w4[base + pos];
        Wv[k] = wv;
        P[k]  = make_float4(xv.x * wv.x, xv.y * wv.y, xv.z * wv.z, xv.w * wv.w);
        sp[ry][pos] = P[k];
        sv[ry][pos] = wv;
    }

    // One sigmoid set per block (9216 % RPB == 0 -> single batch per block)
    if (ry == 0 && tx < 5) {
        const int b = (int)(((long long)blockIdx.x * RPB) / rows_per_batch);
        const float svv = s[b * 5 + tx];
        sg[tx] = 1.0f / (1.0f + __expf(-svv));
    }
    __syncthreads();

    const float g0 = sg[0], g1 = sg[1], g2 = sg[2], g3 = sg[3], g4 = sg[4];

    const int so = 5 - tx;               // partner orbit
    float4 Q[4], V[4];
#pragma unroll
    for (int k = 0; k < 4; k++) {
        Q[k] = sp[ry][so + 6 * k];
        V[k] = sv[ry][so + 6 * k];
    }

#pragma unroll
    for (int m = 0; m < 4; m++) {
        const int m1 = (m + 1) & 3;      // +6  f4  (270deg)
        const int m2 = (m + 2) & 3;      // +12 f4  (180deg)
        const int m3 = (m + 3) & 3;      // +18 f4  (90deg)
        const int kf90  = (4 - m) & 3;   // flip90  slot in partner orbit
        const int kf180 = (1 - m) & 3;   // flip180 slot in partner orbit

        const float4 p0 = P[m],  pa = P[m3], pb = P[m2], pc = P[m1];
        const float4 w0 = Wv[m], wa = Wv[m3], wb = Wv[m2], wc = Wv[m1];
        const float4 qf = Q[kf90],  vf = V[kf90];    // components reversed
        const float4 qg = Q[kf180], vg = V[kf180];   // components reversed

        float4 o;
        {   // c = 0 pairs with partner component .w
            float a = p0.x;
            a = fmaf(g0, pa.x, a); a = fmaf(g1, pb.x, a); a = fmaf(g2, pc.x, a);
            a = fmaf(g3, qf.w, a); a = fmaf(g4, qg.w, a);
            float bden = w0.x;
            bden = fmaf(g0, wa.x, bden); bden = fmaf(g1, wb.x, bden); bden = fmaf(g2, wc.x, bden);
            bden = fmaf(g3, vf.w, bden); bden = fmaf(g4, vg.w, bden);
            o.x = __fdividef(a, bden);
        }
        {   // c = 1 <-> .z
            float a = p0.y;
            a = fmaf(g0, pa.y, a); a = fmaf(g1, pb.y, a); a = fmaf(g2, pc.y, a);
            a = fmaf(g3, qf.z, a); a = fmaf(g4, qg.z, a);
            float bden = w0.y;
            bden = fmaf(g0, wa.y, bden); bden = fmaf(g1, wb.y, bden); bden = fmaf(g2, wc.y, bden);
            bden = fmaf(g3, vf.z, bden); bden = fmaf(g4, vg.z, bden);
            o.y = __fdividef(a, bden);
        }
        {   // c = 2 <-> .y
            float a = p0.z;
            a = fmaf(g0, pa.z, a); a = fmaf(g1, pb.z, a); a = fmaf(g2, pc.z, a);
            a = fmaf(g3, qf.y, a); a = fmaf(g4, qg.y, a);
            float bden = w0.z;
            bden = fmaf(g0, wa.z, bden); bden = fmaf(g1, wb.z, bden); bden = fmaf(g2, wc.z, bden);
            bden = fmaf(g3, vf.y, bden); bden = fmaf(g4, vg.y, bden);
            o.z = __fdividef(a, bden);
        }
        {   // c = 3 <-> .x
            float a = p0.w;
            a = fmaf(g0, pa.w, a); a = fmaf(g1, pb.w, a); a = fmaf(g2, pc.w, a);
            a = fmaf(g3, qf.x, a); a = fmaf(g4, qg.x, a);
            float bden = w0.w;
            bden = fmaf(g0, wa.w, bden); bden = fmaf(g1, wb.w, bden); bden = fmaf(g2, wc.w, bden);
            bden = fmaf(g3, vf.x, bden); bden = fmaf(g4, vg.x, bden);
            o.w = __fdividef(a, bden);
        }

        out4[base + tx + 6 * m] = o;
    }
}

extern "C" void kernel_launch(void* const* d_in, const int* in_sizes, int n_in,
                              void* d_out, int out_size)
{
    const float4* x4 = (const float4*)d_in[0];
    const float*  s  = (const float*)d_in[1];
    const float4* w4 = (const float4*)d_in[2];
    float4* out4 = (float4*)d_out;

    const long long total = in_sizes[0];          // B*C*H*W
    const int B = in_sizes[1] / 5;                // 16
    const long long rows = total / 96;            // B*C*H = 147456
    const int rows_per_batch = (int)(rows / B);   // 9216

    const long long nblocks = rows / RPB;         // 4608
    dim3 block(TPR, RPB);
    symmetry_control_orbit<<<(unsigned)nblocks, block>>>(x4, s, w4, out4, rows_per_batch);
}

// round 4
// speedup vs baseline: 2.8816x; 1.0097x over previous
#include <cuda_runtime.h>

// SymmetryControl (square-symmetry branch), B=16,C=96,H=96,W=96.
// Two-phase, SMEM-bridged:
//   Phase 1: LINEAR lane->float4 mapping (perfectly coalesced LDG.128),
//            stage p = x*w and w into SMEM.
//   Phase 2: orbit compute (thread owns float4 positions {tx,tx+6,tx+12,tx+18}
//            of one row; flip operands come from partner orbit 5-tx).
// Element map (out elem i = 4t+c):
//   shifts: f4 (t+18)%24, (t+12)%24, (t+6)%24, component c
//   flips:  f4 (5-t)%24, (11-t)%24, component 3-c (reversed)

#define W4   24            // float4 per row
#define ROWS 32            // rows per block
#define NT   192           // threads per block
#define PITCH4 30          // SMEM row pitch in float4 (120 words === 24 mod 32)

__global__ __launch_bounds__(NT)
void symmetry_control_coal(const float4* __restrict__ x4,
                           const float*  __restrict__ s,
                           const float4* __restrict__ w4,
                           float4* __restrict__ out4,
                           int rows_per_batch /* C*H = 9216 */)
{
    __shared__ float4 sp[ROWS][PITCH4];   // p = x*w
    __shared__ float4 sv[ROWS][PITCH4];   // w
    __shared__ float  sg[5];

    const int tid = threadIdx.x;

    // ---- Phase 1: coalesced load + stage ---------------------------------
    const size_t blk_f4 = (size_t)blockIdx.x * (ROWS * W4);   // 768 f4 / block
    {
        const int col  = tid % W4;      // 0..23  (constant across j: 192 = 8*24)
        const int row0 = tid / W4;      // 0..7
#pragma unroll
        for (int j = 0; j < 4; j++) {
            const int idx = tid + NT * j;
            const int row = row0 + 8 * j;
            const float4 xv = x4[blk_f4 + idx];
            const float4 wv = w4[blk_f4 + idx];
            sp[row][col] = make_float4(xv.x * wv.x, xv.y * wv.y,
                                       xv.z * wv.z, xv.w * wv.w);
            sv[row][col] = wv;
        }
    }

    // One sigmoid set per block (9216 % ROWS == 0 -> single batch per block)
    if (tid < 5) {
        const int b = (int)(((long long)blockIdx.x * ROWS) / rows_per_batch);
        const float svv = s[b * 5 + tid];
        sg[tid] = 1.0f / (1.0f + __expf(-svv));
    }
    __syncthreads();

    // ---- Phase 2: orbit compute ------------------------------------------
    const int tx = tid % 6;             // orbit id
    const int ry = tid / 6;             // row within block, 0..31
    const int so = 5 - tx;              // partner orbit

    const float g0 = sg[0], g1 = sg[1], g2 = sg[2], g3 = sg[3], g4 = sg[4];

    float4 P[4], Wv[4], Q[4], V[4];
#pragma unroll
    for (int k = 0; k < 4; k++) {
        P[k]  = sp[ry][tx + 6 * k];     // own orbit p     (conflict-free)
        Wv[k] = sv[ry][tx + 6 * k];     // own orbit w
        Q[k]  = sp[ry][so + 6 * k];     // partner orbit p (<=2-way)
        V[k]  = sv[ry][so + 6 * k];     // partner orbit w
    }

    const size_t rowbase = (size_t)(blockIdx.x * ROWS + ry) * W4;

#pragma unroll
    for (int m = 0; m < 4; m++) {
        const int m1 = (m + 1) & 3;      // +6  f4 (270deg)
        const int m2 = (m + 2) & 3;      // +12 f4 (180deg)
        const int m3 = (m + 3) & 3;      // +18 f4 (90deg)
        const int kf90  = (4 - m) & 3;   // flip90  slot in partner orbit
        const int kf180 = (1 - m) & 3;   // flip180 slot in partner orbit

        const float4 p0 = P[m],  pa = P[m3],  pb = P[m2],  pc = P[m1];
        const float4 w0 = Wv[m], wa = Wv[m3], wb = Wv[m2], wc = Wv[m1];
        const float4 qf = Q[kf90],  vf = V[kf90];    // components reversed
        const float4 qg = Q[kf180], vg = V[kf180];   // components reversed

        float4 o;
        {   // c = 0 <-> partner .w
            float a = p0.x;
            a = fmaf(g0, pa.x, a); a = fmaf(g1, pb.x, a); a = fmaf(g2, pc.x, a);
            a = fmaf(g3, qf.w, a); a = fmaf(g4, qg.w, a);
            float d = w0.x;
            d = fmaf(g0, wa.x, d); d = fmaf(g1, wb.x, d); d = fmaf(g2, wc.x, d);
            d = fmaf(g3, vf.w, d); d = fmaf(g4, vg.w, d);
            o.x = __fdividef(a, d);
        }
        {   // c = 1 <-> .z
            float a = p0.y;
            a = fmaf(g0, pa.y, a); a = fmaf(g1, pb.y, a); a = fmaf(g2, pc.y, a);
            a = fmaf(g3, qf.z, a); a = fmaf(g4, qg.z, a);
            float d = w0.y;
            d = fmaf(g0, wa.y, d); d = fmaf(g1, wb.y, d); d = fmaf(g2, wc.y, d);
            d = fmaf(g3, vf.z, d); d = fmaf(g4, vg.z, d);
            o.y = __fdividef(a, d);
        }
        {   // c = 2 <-> .y
            float a = p0.z;
            a = fmaf(g0, pa.z, a); a = fmaf(g1, pb.z, a); a = fmaf(g2, pc.z, a);
            a = fmaf(g3, qf.y, a); a = fmaf(g4, qg.y, a);
            float d = w0.z;
            d = fmaf(g0, wa.z, d); d = fmaf(g1, wb.z, d); d = fmaf(g2, wc.z, d);
            d = fmaf(g3, vf.y, d); d = fmaf(g4, vg.y, d);
            o.z = __fdividef(a, d);
        }
        {   // c = 3 <-> .x
            float a = p0.w;
            a = fmaf(g0, pa.w, a); a = fmaf(g1, pb.w, a); a = fmaf(g2, pc.w, a);
            a = fmaf(g3, qf.x, a); a = fmaf(g4, qg.x, a);
            float d = w0.w;
            d = fmaf(g0, wa.w, d); d = fmaf(g1, wb.w, d); d = fmaf(g2, wc.w, d);
            d = fmaf(g3, vf.x, d); d = fmaf(g4, vg.x, d);
            o.w = __fdividef(a, d);
        }

        out4[rowbase + tx + 6 * m] = o;
    }
}

extern "C" void kernel_launch(void* const* d_in, const int* in_sizes, int n_in,
                              void* d_out, int out_size)
{
    const float4* x4 = (const float4*)d_in[0];
    const float*  s  = (const float*)d_in[1];
    const float4* w4 = (const float4*)d_in[2];
    float4* out4 = (float4*)d_out;

    const long long total = in_sizes[0];          // B*C*H*W
    const int B = in_sizes[1] / 5;                // 16
    const long long rows = total / 96;            // B*C*H = 147456
    const int rows_per_batch = (int)(rows / B);   // 9216

    const long long nblocks = rows / ROWS;        // 4608
    symmetry_control_coal<<<(unsigned)nblocks, NT>>>(x4, s, w4, out4, rows_per_batch);
}